// round 8
// baseline (speedup 1.0000x reference)
#include <cuda_runtime.h>
#include <cuda_bf16.h>
#include <cstdint>

#define BATCH 2
#define CH 64
#define DI 32
#define NP 6400
#define SPL 20
#define QTILES 100              // number of 64-query tiles = NP/64
#define ITEMS (BATCH * QTILES * SPL)   // 4000
#define TILES_PER 5             // 320 keys per item / 64
#define LOG2E 1.4426950408889634f

typedef uint32_t u32;
typedef unsigned long long u64;

// ---------------- scratch ----------------
__device__ __nv_bfloat16 g_Qh[BATCH * NP * DI], g_Ql[BATCH * NP * DI];
__device__ uint4 g_Kz[BATCH * NP * 8];          // per key: 8 x 16B swizzled {bh0,bh1,bl0,bl1}
__device__ uint4 g_Vz[BATCH * DI * QTILES * 16];// per (d, 64-key chunk): 16 x 16B swizzled
__device__ float g_thn[BATCH * NP];
__device__ unsigned g_phimax[BATCH];
__device__ unsigned g_ctr;
__device__ float g_acc[BATCH * SPL * NP * DI];
__device__ float g_lp[BATCH * SPL * NP];

// ---------------- helpers ----------------
__device__ __forceinline__ u64 f2fma(u64 a, u64 b, u64 c) {
    u64 d; asm("fma.rn.f32x2 %0,%1,%2,%3;" : "=l"(d) : "l"(a), "l"(b), "l"(c)); return d;
}
__device__ __forceinline__ u64 f2add(u64 a, u64 b) {
    u64 d; asm("add.rn.f32x2 %0,%1,%2;" : "=l"(d) : "l"(a), "l"(b)); return d;
}
__device__ __forceinline__ float f2hadd(u64 a) {
    float lo, hi; asm("mov.b64 {%0,%1},%2;" : "=f"(lo), "=f"(hi) : "l"(a)); return lo + hi;
}
__device__ __forceinline__ u32 pkbf(float hi, float lo) {
    u32 r; asm("cvt.rn.bf16x2.f32 %0,%1,%2;" : "=r"(r) : "f"(hi), "f"(lo)); return r;
}
__device__ __forceinline__ float bflo(u32 p) { return __uint_as_float(p << 16); }
__device__ __forceinline__ float bfhi(u32 p) { return __uint_as_float(p & 0xffff0000u); }
__device__ __forceinline__ float ex2f(float x) {
    float r; asm("ex2.approx.f32 %0,%1;" : "=f"(r) : "f"(x)); return r;
}
__device__ __forceinline__ void mma_bf16(float* c, const u32* a, u32 b0, u32 b1) {
    asm("mma.sync.aligned.m16n8k16.row.col.f32.bf16.bf16.f32 "
        "{%0,%1,%2,%3},{%4,%5,%6,%7},{%8,%9},{%0,%1,%2,%3};"
        : "+f"(c[0]), "+f"(c[1]), "+f"(c[2]), "+f"(c[3])
        : "r"(a[0]), "r"(a[1]), "r"(a[2]), "r"(a[3]), "r"(b0), "r"(b1));
}
__device__ __forceinline__ void cpa16(u32 sa, const void* g) {
    asm volatile("cp.async.cg.shared.global [%0],[%1],16;" :: "r"(sa), "l"(g) : "memory");
}
__device__ __forceinline__ u32 smaddr(const void* p) {
    u32 a; asm("{ .reg .u64 t; cvta.to.shared.u64 t,%1; cvt.u32.u64 %0,t; }" : "=r"(a) : "l"(p));
    return a;
}

// ---------------------------------------------------------------------------
// Stage 1: projection. grid (NP/128 = 50, 3, 2), 128 threads; blockIdx.y = matrix.
// m=0: theta(*log2e) -> Qh/Ql + thn; m=1: phi -> swizzled g_Kz + phimax;
// m=2: g -> swizzled transposed g_Vz.
// ---------------------------------------------------------------------------
__global__ void __launch_bounds__(128) proj_kernel(
    const float* __restrict__ x,
    const float* __restrict__ theta_w,
    const float* __restrict__ phi_w,
    const float* __restrict__ gw)
{
    __shared__ __align__(16) float xs[CH * 128];      // 32KB
    __shared__ __align__(16) float wT[CH * DI];       // 8KB

    const int b = blockIdx.z, m = blockIdx.y, n0 = blockIdx.x * 128;
    const int wt = threadIdx.x;
    const float* wsrc = (m == 0) ? theta_w : (m == 1) ? phi_w : gw;

    for (int idx = wt; idx < DI * CH; idx += 128) {
        int i = idx / CH, c = idx % CH;
        wT[c * DI + i] = wsrc[idx];
    }
    const float* xb = x + b * CH * NP + n0;
    for (int idx = wt; idx < CH * 128; idx += 128)
        xs[idx] = xb[(idx >> 7) * NP + (idx & 127)];
    __syncthreads();

    u64 acc2[16];
    #pragma unroll
    for (int i = 0; i < 16; i++) acc2[i] = 0ull;
    #pragma unroll 4
    for (int c = 0; c < CH; c++) {
        float xv = xs[c * 128 + wt];
        u64 x2; asm("mov.b64 %0,{%1,%1};" : "=l"(x2) : "f"(xv));
        const u64* w2 = (const u64*)(wT + c * DI);
        #pragma unroll
        for (int i2 = 0; i2 < 16; i2++) acc2[i2] = f2fma(w2[i2], x2, acc2[i2]);
    }
    float v[DI];
    #pragma unroll
    for (int i2 = 0; i2 < 16; i2++)
        asm("mov.b64 {%0,%1},%2;" : "=f"(v[2 * i2]), "=f"(v[2 * i2 + 1]) : "l"(acc2[i2]));

    const int n = n0 + wt;
    if (m == 0) {
        #pragma unroll
        for (int i = 0; i < DI; i++) v[i] *= LOG2E;
        float nrm = 0.f;
        u32 hb[16], lb[16];
        #pragma unroll
        for (int i2 = 0; i2 < 16; i2++) {
            float f0 = v[2 * i2], f1 = v[2 * i2 + 1];
            nrm = fmaf(f0, f0, fmaf(f1, f1, nrm));
            u32 h = pkbf(f1, f0);
            hb[i2] = h;
            lb[i2] = pkbf(f1 - bfhi(h), f0 - bflo(h));
        }
        uint4* hp = (uint4*)(g_Qh + (b * NP + n) * DI);
        uint4* lp = (uint4*)(g_Ql + (b * NP + n) * DI);
        #pragma unroll
        for (int i = 0; i < 4; i++) {
            hp[i] = make_uint4(hb[4*i], hb[4*i+1], hb[4*i+2], hb[4*i+3]);
            lp[i] = make_uint4(lb[4*i], lb[4*i+1], lb[4*i+2], lb[4*i+3]);
        }
        g_thn[b * NP + n] = nrm;
    } else if (m == 1) {
        float nrm = 0.f;
        u32 hb[16], lb[16];
        #pragma unroll
        for (int i2 = 0; i2 < 16; i2++) {
            float f0 = v[2 * i2], f1 = v[2 * i2 + 1];
            nrm = fmaf(f0, f0, fmaf(f1, f1, nrm));
            u32 h = pkbf(f1, f0);
            hb[i2] = h;
            lb[i2] = pkbf(f1 - bfhi(h), f0 - bflo(h));
        }
        // swizzled 16B blocks: blk = (s ^ (n&1))*4 + t4
        uint4* dst = (uint4*)g_Kz + (b * NP + n) * 8;
        #pragma unroll
        for (int s = 0; s < 2; s++)
            #pragma unroll
            for (int t4 = 0; t4 < 4; t4++) {
                int blk = ((s ^ (n & 1)) << 2) + t4;
                dst[blk] = make_uint4(hb[8*s + t4], hb[8*s + 4 + t4],
                                      lb[8*s + t4], lb[8*s + 4 + t4]);
            }
        unsigned mx = __reduce_max_sync(0xffffffffu, __float_as_uint(nrm));
        if ((wt & 31) == 0) atomicMax(&g_phimax[b], mx);
    } else {
        // stage transpose in smem (overwrite xs), then swizzled copy-out
        __syncthreads();
        u32* vh = (u32*)xs;            // [32][64] u32 (bf16x2 pairs along keys)
        u32* vl = vh + 32 * 64;
        __nv_bfloat16* vhb = (__nv_bfloat16*)vh;
        __nv_bfloat16* vlb = (__nv_bfloat16*)vl;
        #pragma unroll
        for (int d = 0; d < DI; d++) {
            __nv_bfloat16 h = __float2bfloat16(v[d]);
            vhb[d * 128 + wt] = h;
            vlb[d * 128 + wt] = __float2bfloat16(v[d] - __bfloat162float(h));
        }
        __syncthreads();
        // copy-out: 1024 blocks: idx: d(5b) | c(1b) | s4(2b) | t4(2b)
        #pragma unroll
        for (int i = 0; i < 8; i++) {
            int idx = wt + 128 * i;
            int d = idx >> 5, rem = idx & 31;
            int c = rem >> 4, s4 = (rem >> 2) & 3, t4 = rem & 3;
            int kp = c * 32 + 8 * s4 + t4;          // u32 pair index within row
            uint4 val = make_uint4(vh[d * 64 + kp], vh[d * 64 + kp + 4],
                                   vl[d * 64 + kp], vl[d * 64 + kp + 4]);
            int blk = ((s4 ^ (d & 1)) << 2) + t4;
            g_Vz[((b * DI + d) * QTILES + (n0 >> 6) + c) * 16 + blk] = val;
        }
    }
}

// ---------------------------------------------------------------------------
// Stage 2: persistent work-stealing bf16x3 flash attention.
// grid 592, 128 thr. item = (b, qtile, split of 320 keys = 5 tiles).
// smem: 2 x (K 8KB + V 8KB).
// ---------------------------------------------------------------------------
#define KBUF 16384

__global__ void __launch_bounds__(128, 4) attn_kernel()
{
    __shared__ __align__(16) char smem[2 * KBUF];
    __shared__ unsigned sm_w;

    const int tid = threadIdx.x, w = tid >> 5, lane = tid & 31;
    const int g = lane >> 2, t4 = lane & 3;
    const int gp = g & 1;
    const u32 smbase = smaddr(smem);

    int tc = 0;   // tile parity counter (carries buffer parity across items)

    for (;;) {
        __syncthreads();
        if (tid == 0) sm_w = atomicAdd(&g_ctr, 1u);
        __syncthreads();
        const unsigned wi = sm_w;
        if (wi >= ITEMS) break;

        const int b = wi / (QTILES * SPL);
        const int r = wi % (QTILES * SPL);
        const int qt = r / SPL, split = r % SPL;
        const int n0 = qt * 64, k0s = split * 320;
        const int q0 = n0 + w * 16 + g, q1 = q0 + 8;

        auto prefetch = [&](int k0, int buf) {
            const u32 bb = smbase + buf * KBUF;
            const uint4* ks = g_Kz + (b * NP + k0) * 8;
            const uint4* vs = g_Vz + (b * DI * QTILES + (k0 >> 6)) * 16;
            #pragma unroll
            for (int i = 0; i < 4; i++) {
                int idx = tid + 128 * i;
                cpa16(bb + idx * 16, ks + idx);
                int d = idx >> 4, blk = idx & 15;
                cpa16(bb + 8192 + idx * 16, vs + d * QTILES * 16 + blk);
            }
            asm volatile("cp.async.commit_group;" ::: "memory");
        };
        prefetch(k0s, tc & 1);

        // Q fragments
        u32 ah[2][4], al[2][4];
        {
            const u32* Qh32 = (const u32*)g_Qh;
            const u32* Ql32 = (const u32*)g_Ql;
            const int r0 = (b * NP + q0) * (DI / 2), r1 = (b * NP + q1) * (DI / 2);
            #pragma unroll
            for (int s = 0; s < 2; s++) {
                ah[s][0] = Qh32[r0 + t4 + 8 * s];
                ah[s][1] = Qh32[r1 + t4 + 8 * s];
                ah[s][2] = Qh32[r0 + t4 + 4 + 8 * s];
                ah[s][3] = Qh32[r1 + t4 + 4 + 8 * s];
                al[s][0] = Ql32[r0 + t4 + 8 * s];
                al[s][1] = Ql32[r1 + t4 + 8 * s];
                al[s][2] = Ql32[r0 + t4 + 4 + 8 * s];
                al[s][3] = Ql32[r1 + t4 + 4 + 8 * s];
            }
        }
        const float pm = sqrtf(__uint_as_float(g_phimax[b]));
        const float bd0 = sqrtf(g_thn[b * NP + q0]) * pm;
        const float bd1 = sqrtf(g_thn[b * NP + q1]) * pm;

        float o[4][4];
        #pragma unroll
        for (int i = 0; i < 4; i++)
            #pragma unroll
            for (int j = 0; j < 4; j++) o[i][j] = 0.f;
        float l0 = 0.f, l1 = 0.f;

        for (int t = 0; t < TILES_PER; t++) {
            asm volatile("cp.async.wait_group 0;" ::: "memory");
            __syncthreads();
            if (t + 1 < TILES_PER) prefetch(k0s + (t + 1) * 64, (tc + 1) & 1);

            const char* bb = smem + (tc & 1) * KBUF;
            const char* vb0 = bb + 8192;

            // ---- S = Q K^T (bf16x3), acc pre-init to -bound ----
            float sc[8][4];
            #pragma unroll
            for (int j = 0; j < 8; j++) {
                sc[j][0] = -bd0; sc[j][1] = -bd0;
                sc[j][2] = -bd1; sc[j][3] = -bd1;
            }
            #pragma unroll
            for (int s = 0; s < 2; s++) {
                const int so = (((s ^ gp) << 2) + t4) << 4;
                #pragma unroll
                for (int j = 0; j < 8; j++) {
                    uint4 kk = *(const uint4*)(bb + ((8 * j + g) << 7) + so);
                    mma_bf16(sc[j], ah[s], kk.x, kk.y);
                    mma_bf16(sc[j], al[s], kk.x, kk.y);
                    mma_bf16(sc[j], ah[s], kk.z, kk.w);
                }
            }

            // ---- exp2 -> P fragments ----
            u32 ph[4][4], pl[4][4];
            #pragma unroll
            for (int j = 0; j < 8; j++) {
                float p0 = ex2f(sc[j][0]);
                float p1 = ex2f(sc[j][1]);
                float p2 = ex2f(sc[j][2]);
                float p3 = ex2f(sc[j][3]);
                l0 += p0 + p1; l1 += p2 + p3;
                u32 h01 = pkbf(p1, p0), h23 = pkbf(p3, p2);
                u32 lo01 = pkbf(p1 - bfhi(h01), p0 - bflo(h01));
                u32 lo23 = pkbf(p3 - bfhi(h23), p2 - bflo(h23));
                const int s4 = j >> 1, hf = j & 1;
                ph[s4][2 * hf] = h01; ph[s4][2 * hf + 1] = h23;
                pl[s4][2 * hf] = lo01; pl[s4][2 * hf + 1] = lo23;
            }

            // ---- O += P V (bf16x3) ----
            #pragma unroll
            for (int s4 = 0; s4 < 4; s4++) {
                const int so = (((s4 ^ gp) << 2) + t4) << 4;
                #pragma unroll
                for (int j2 = 0; j2 < 4; j2++) {
                    uint4 vv = *(const uint4*)(vb0 + ((8 * j2 + g) << 8) + so);
                    mma_bf16(o[j2], ph[s4], vv.x, vv.y);
                    mma_bf16(o[j2], pl[s4], vv.x, vv.y);
                    mma_bf16(o[j2], ph[s4], vv.z, vv.w);
                }
            }
            tc++;
        }

        l0 += __shfl_xor_sync(0xffffffffu, l0, 1);
        l0 += __shfl_xor_sync(0xffffffffu, l0, 2);
        l1 += __shfl_xor_sync(0xffffffffu, l1, 1);
        l1 += __shfl_xor_sync(0xffffffffu, l1, 2);

        const int pb = (b * SPL + split) * NP;
        #pragma unroll
        for (int j2 = 0; j2 < 4; j2++) {
            *(float2*)(g_acc + (pb + q0) * DI + 8 * j2 + 2 * t4) = make_float2(o[j2][0], o[j2][1]);
            *(float2*)(g_acc + (pb + q1) * DI + 8 * j2 + 2 * t4) = make_float2(o[j2][2], o[j2][3]);
        }
        if (t4 == 0) { g_lp[pb + q0] = l0; g_lp[pb + q1] = l1; }
    }
}

// ---------------------------------------------------------------------------
// Stage 3: merge SPL partials + output projection + residual.
// ---------------------------------------------------------------------------
__global__ void __launch_bounds__(128) merge_kernel(
    const float* __restrict__ x,
    const float* __restrict__ w_w,
    float* __restrict__ out)
{
    __shared__ __align__(16) float ws[CH * DI];
    const int b = blockIdx.y, tid = threadIdx.x;
    const int n = blockIdx.x * 128 + tid;

    for (int i = tid; i < CH * DI; i += 128) ws[i] = w_w[i];
    __syncthreads();

    float l = 0.f;
    u64 y2[16];
    #pragma unroll
    for (int i = 0; i < 16; i++) y2[i] = 0ull;
    #pragma unroll 4
    for (int s = 0; s < SPL; s++) {
        l += g_lp[(b * SPL + s) * NP + n];
        const u64* ap = (const u64*)(g_acc + ((b * SPL + s) * NP + n) * DI);
        #pragma unroll
        for (int i2 = 0; i2 < 16; i2++) y2[i2] = f2add(y2[i2], ap[i2]);
    }
    const float inv = 1.f / l;
    u64 inv2; asm("mov.b64 %0,{%1,%1};" : "=l"(inv2) : "f"(inv));
    #pragma unroll
    for (int i2 = 0; i2 < 16; i2++) {
        u64 z = 0ull;
        y2[i2] = f2fma(y2[i2], inv2, z);
    }

    const float* xb = x + b * CH * NP + n;
    float* ob = out + b * CH * NP + n;
    #pragma unroll 2
    for (int c = 0; c < CH; c++) {
        const u64* w2 = (const u64*)(ws + c * DI);
        u64 o2 = 0ull;
        #pragma unroll
        for (int i2 = 0; i2 < 16; i2++) o2 = f2fma(w2[i2], y2[i2], o2);
        ob[c * NP] = xb[c * NP] + f2hadd(o2);
    }
}

// ---------------------------------------------------------------------------
extern "C" void kernel_launch(void* const* d_in, const int* in_sizes, int n_in,
                              void* d_out, int out_size)
{
    const float* x       = (const float*)d_in[0];
    const float* gw      = (const float*)d_in[1];
    const float* theta_w = (const float*)d_in[2];
    const float* phi_w   = (const float*)d_in[3];
    const float* w_w     = (const float*)d_in[4];
    float* out           = (float*)d_out;

    void* pm = nullptr; cudaGetSymbolAddress(&pm, g_phimax);
    cudaMemsetAsync(pm, 0, sizeof(unsigned) * BATCH);
    void* pc = nullptr; cudaGetSymbolAddress(&pc, g_ctr);
    cudaMemsetAsync(pc, 0, sizeof(unsigned));

    dim3 gp(NP / 128, 3, BATCH);            // FIX: 50 query tiles of 128, not QTILES(=100)
    proj_kernel<<<gp, 128>>>(x, theta_w, phi_w, gw);

    attn_kernel<<<592, 128>>>();

    dim3 gm(NP / 128, BATCH);
    merge_kernel<<<gm, 128>>>(x, w_w, out);
}

// round 9
// speedup vs baseline: 1.0478x; 1.0478x over previous
#include <cuda_runtime.h>
#include <cuda_bf16.h>
#include <cstdint>

#define BATCH 2
#define CH 64
#define DI 32
#define NP 6400
#define SPL 10
#define QTCH 100               // 64-key chunks per batch (g_Vz stride)
#define TPI 10                 // tiles per item (640 keys)
#define ITEMS 1000             // 2 b * 50 qtiles(128) * 10 splits
#define LOG2E 1.4426950408889634f

typedef uint32_t u32;
typedef unsigned long long u64;

// ---------------- scratch ----------------
__device__ __nv_bfloat16 g_Qh[BATCH * NP * DI], g_Ql[BATCH * NP * DI];
__device__ uint4 g_Kz[BATCH * NP * 8];
__device__ uint4 g_Vz[BATCH * DI * QTCH * 16];
__device__ float g_thn[BATCH * NP];
__device__ unsigned g_phimax[BATCH];
__device__ unsigned g_ctr;
__device__ float g_acc[BATCH * SPL * NP * DI];
__device__ float g_lp[BATCH * SPL * NP];

// ---------------- helpers ----------------
__device__ __forceinline__ u64 f2fma(u64 a, u64 b, u64 c) {
    u64 d; asm("fma.rn.f32x2 %0,%1,%2,%3;" : "=l"(d) : "l"(a), "l"(b), "l"(c)); return d;
}
__device__ __forceinline__ u64 f2add(u64 a, u64 b) {
    u64 d; asm("add.rn.f32x2 %0,%1,%2;" : "=l"(d) : "l"(a), "l"(b)); return d;
}
__device__ __forceinline__ float f2hadd(u64 a) {
    float lo, hi; asm("mov.b64 {%0,%1},%2;" : "=f"(lo), "=f"(hi) : "l"(a)); return lo + hi;
}
__device__ __forceinline__ u32 pkbf(float hi, float lo) {
    u32 r; asm("cvt.rn.bf16x2.f32 %0,%1,%2;" : "=r"(r) : "f"(hi), "f"(lo)); return r;
}
__device__ __forceinline__ float bflo(u32 p) { return __uint_as_float(p << 16); }
__device__ __forceinline__ float bfhi(u32 p) { return __uint_as_float(p & 0xffff0000u); }
__device__ __forceinline__ float ex2f(float x) {
    float r; asm("ex2.approx.f32 %0,%1;" : "=f"(r) : "f"(x)); return r;
}
__device__ __forceinline__ void mma_bf16(float* c, const u32* a, u32 b0, u32 b1) {
    asm("mma.sync.aligned.m16n8k16.row.col.f32.bf16.bf16.f32 "
        "{%0,%1,%2,%3},{%4,%5,%6,%7},{%8,%9},{%0,%1,%2,%3};"
        : "+f"(c[0]), "+f"(c[1]), "+f"(c[2]), "+f"(c[3])
        : "r"(a[0]), "r"(a[1]), "r"(a[2]), "r"(a[3]), "r"(b0), "r"(b1));
}
__device__ __forceinline__ void cpa16(u32 sa, const void* g) {
    asm volatile("cp.async.cg.shared.global [%0],[%1],16;" :: "r"(sa), "l"(g) : "memory");
}
__device__ __forceinline__ u32 smaddr(const void* p) {
    u32 a; asm("{ .reg .u64 t; cvta.to.shared.u64 t,%1; cvt.u32.u64 %0,t; }" : "=r"(a) : "l"(p));
    return a;
}

// ---------------------------------------------------------------------------
// Stage 1: projection. grid (50, 3, 2), 128 threads; blockIdx.y = matrix.
// ---------------------------------------------------------------------------
__global__ void __launch_bounds__(128) proj_kernel(
    const float* __restrict__ x,
    const float* __restrict__ theta_w,
    const float* __restrict__ phi_w,
    const float* __restrict__ gw)
{
    __shared__ __align__(16) float xs[CH * 128];
    __shared__ __align__(16) float wT[CH * DI];

    const int b = blockIdx.z, m = blockIdx.y, n0 = blockIdx.x * 128;
    const int wt = threadIdx.x;
    const float* wsrc = (m == 0) ? theta_w : (m == 1) ? phi_w : gw;

    for (int idx = wt; idx < DI * CH; idx += 128) {
        int i = idx / CH, c = idx % CH;
        wT[c * DI + i] = wsrc[idx];
    }
    const float* xb = x + b * CH * NP + n0;
    for (int idx = wt; idx < CH * 128; idx += 128)
        xs[idx] = xb[(idx >> 7) * NP + (idx & 127)];
    __syncthreads();

    u64 acc2[16];
    #pragma unroll
    for (int i = 0; i < 16; i++) acc2[i] = 0ull;
    #pragma unroll 4
    for (int c = 0; c < CH; c++) {
        float xv = xs[c * 128 + wt];
        u64 x2; asm("mov.b64 %0,{%1,%1};" : "=l"(x2) : "f"(xv));
        const ulonglong2* w2 = (const ulonglong2*)(wT + c * DI);
        #pragma unroll
        for (int i4 = 0; i4 < 8; i4++) {
            ulonglong2 ww = w2[i4];
            acc2[2 * i4]     = f2fma(ww.x, x2, acc2[2 * i4]);
            acc2[2 * i4 + 1] = f2fma(ww.y, x2, acc2[2 * i4 + 1]);
        }
    }
    float v[DI];
    #pragma unroll
    for (int i2 = 0; i2 < 16; i2++)
        asm("mov.b64 {%0,%1},%2;" : "=f"(v[2 * i2]), "=f"(v[2 * i2 + 1]) : "l"(acc2[i2]));

    const int n = n0 + wt;
    if (m == 0) {
        #pragma unroll
        for (int i = 0; i < DI; i++) v[i] *= LOG2E;
        float nrm = 0.f;
        u32 hb[16], lb[16];
        #pragma unroll
        for (int i2 = 0; i2 < 16; i2++) {
            float f0 = v[2 * i2], f1 = v[2 * i2 + 1];
            nrm = fmaf(f0, f0, fmaf(f1, f1, nrm));
            u32 h = pkbf(f1, f0);
            hb[i2] = h;
            lb[i2] = pkbf(f1 - bfhi(h), f0 - bflo(h));
        }
        uint4* hp = (uint4*)(g_Qh + (b * NP + n) * DI);
        uint4* lp = (uint4*)(g_Ql + (b * NP + n) * DI);
        #pragma unroll
        for (int i = 0; i < 4; i++) {
            hp[i] = make_uint4(hb[4*i], hb[4*i+1], hb[4*i+2], hb[4*i+3]);
            lp[i] = make_uint4(lb[4*i], lb[4*i+1], lb[4*i+2], lb[4*i+3]);
        }
        g_thn[b * NP + n] = nrm;
    } else if (m == 1) {
        float nrm = 0.f;
        u32 hb[16], lb[16];
        #pragma unroll
        for (int i2 = 0; i2 < 16; i2++) {
            float f0 = v[2 * i2], f1 = v[2 * i2 + 1];
            nrm = fmaf(f0, f0, fmaf(f1, f1, nrm));
            u32 h = pkbf(f1, f0);
            hb[i2] = h;
            lb[i2] = pkbf(f1 - bfhi(h), f0 - bflo(h));
        }
        uint4* dst = (uint4*)g_Kz + (b * NP + n) * 8;
        #pragma unroll
        for (int s = 0; s < 2; s++)
            #pragma unroll
            for (int t4 = 0; t4 < 4; t4++) {
                int blk = ((s ^ (n & 1)) << 2) + t4;
                dst[blk] = make_uint4(hb[8*s + t4], hb[8*s + 4 + t4],
                                      lb[8*s + t4], lb[8*s + 4 + t4]);
            }
        unsigned mx = __reduce_max_sync(0xffffffffu, __float_as_uint(nrm));
        if ((wt & 31) == 0) atomicMax(&g_phimax[b], mx);
    } else {
        __syncthreads();
        u32* vh = (u32*)xs;
        u32* vl = vh + 32 * 64;
        __nv_bfloat16* vhb = (__nv_bfloat16*)vh;
        __nv_bfloat16* vlb = (__nv_bfloat16*)vl;
        #pragma unroll
        for (int d = 0; d < DI; d++) {
            __nv_bfloat16 h = __float2bfloat16(v[d]);
            vhb[d * 128 + wt] = h;
            vlb[d * 128 + wt] = __float2bfloat16(v[d] - __bfloat162float(h));
        }
        __syncthreads();
        #pragma unroll
        for (int i = 0; i < 8; i++) {
            int idx = wt + 128 * i;
            int d = idx >> 5, rem = idx & 31;
            int c = rem >> 4, s4 = (rem >> 2) & 3, t4 = rem & 3;
            int kp = c * 32 + 8 * s4 + t4;
            uint4 val = make_uint4(vh[d * 64 + kp], vh[d * 64 + kp + 4],
                                   vl[d * 64 + kp], vl[d * 64 + kp + 4]);
            int blk = ((s4 ^ (d & 1)) << 2) + t4;
            g_Vz[((b * DI + d) * QTCH + (n0 >> 6) + c) * 16 + blk] = val;
        }
    }
}

// ---------------------------------------------------------------------------
// Stage 2: pipelined persistent flash attention. 296 CTAs x 256 thr (8 warps).
// item = (b, 128-query tile, 640-key split). Next item's KV tile0 + Q tile are
// prefetched during the current item's last tile -> no inter-item bubble.
// smem: kv[2][16KB] + Q[16KB] + next-id.
// ---------------------------------------------------------------------------
#define KBUF 16384
#define QOFF 32768
#define SMN  49152
#define ASMEM 49168

__global__ void __launch_bounds__(256, 2) attn_kernel()
{
    extern __shared__ __align__(16) char smem[];
    const int tid = threadIdx.x, w = tid >> 5, lane = tid & 31;
    const int g = lane >> 2, t4 = lane & 3;
    const int gp = g & 1;
    const u32 smbase = smaddr(smem);
    volatile u32* sm_next = (volatile u32*)(smem + SMN);

    auto prefetchKV = [&](int b, int k0, int buf) {
        const u32 bb = smbase + buf * KBUF;
        const uint4* ks = g_Kz + (b * NP + k0) * 8;
        const uint4* vs = g_Vz + (b * DI * QTCH + (k0 >> 6)) * 16;
        #pragma unroll
        for (int i = 0; i < 2; i++) {
            int idx = tid + 256 * i;
            cpa16(bb + idx * 16, ks + idx);
            int d = idx >> 4, blk = idx & 15;
            cpa16(bb + 8192 + idx * 16, vs + d * QTCH * 16 + blk);
        }
    };
    auto prefetchQ = [&](int b, int n0) {
        const uint4* qh = (const uint4*)(g_Qh + (b * NP + n0) * DI);
        const uint4* ql = (const uint4*)(g_Ql + (b * NP + n0) * DI);
        #pragma unroll
        for (int i = 0; i < 2; i++) {
            int idx = tid + 256 * i;
            cpa16(smbase + QOFF + idx * 16, qh + idx);
            cpa16(smbase + QOFF + 8192 + idx * 16, ql + idx);
        }
    };

    // first item
    if (tid == 0) *sm_next = atomicAdd(&g_ctr, 1u);
    __syncthreads();
    unsigned wi = *sm_next;
    if (wi < ITEMS) {
        int b = wi / 500, r = wi % 500;
        prefetchKV(b, (r % SPL) * 640, 0);
        prefetchQ(b, (r / SPL) * 128);
        asm volatile("cp.async.commit_group;" ::: "memory");
    }
    int tc = 0;

    while (wi < ITEMS) {
        const int b = wi / 500;
        const int r = wi % 500;
        const int qt = r / SPL, sp = r % SPL;
        const int n0 = qt * 128, k0s = sp * 640;
        const int lr0 = w * 16 + g;
        const int q0 = n0 + lr0, q1 = q0 + 8;

        const float pm = sqrtf(__uint_as_float(g_phimax[b]));
        const float bd0 = sqrtf(g_thn[b * NP + q0]) * pm;
        const float bd1 = sqrtf(g_thn[b * NP + q1]) * pm;

        float o[4][4];
        #pragma unroll
        for (int i = 0; i < 4; i++)
            #pragma unroll
            for (int j = 0; j < 4; j++) o[i][j] = 0.f;
        float l0 = 0.f, l1 = 0.f;
        u32 ah[2][4], al[2][4];
        unsigned nwi = ITEMS;

        for (int t = 0; t < TPI; t++) {
            asm volatile("cp.async.wait_group 0;" ::: "memory");
            __syncthreads();

            if (t == 0) {
                const u32* qh32 = (const u32*)(smem + QOFF);
                const u32* ql32 = (const u32*)(smem + QOFF + 8192);
                const int r0 = lr0 * 16, r1 = (lr0 + 8) * 16;
                #pragma unroll
                for (int s = 0; s < 2; s++) {
                    ah[s][0] = qh32[r0 + t4 + 8 * s];
                    ah[s][1] = qh32[r1 + t4 + 8 * s];
                    ah[s][2] = qh32[r0 + t4 + 4 + 8 * s];
                    ah[s][3] = qh32[r1 + t4 + 4 + 8 * s];
                    al[s][0] = ql32[r0 + t4 + 8 * s];
                    al[s][1] = ql32[r1 + t4 + 8 * s];
                    al[s][2] = ql32[r0 + t4 + 4 + 8 * s];
                    al[s][3] = ql32[r1 + t4 + 4 + 8 * s];
                }
            }
            if (t == TPI - 2 && tid == 0) *sm_next = atomicAdd(&g_ctr, 1u);
            if (t < TPI - 1) {
                prefetchKV(b, k0s + (t + 1) * 64, (tc + 1) & 1);
                asm volatile("cp.async.commit_group;" ::: "memory");
            } else {
                nwi = *sm_next;
                if (nwi < ITEMS) {
                    int nb = nwi / 500, nr = nwi % 500;
                    prefetchKV(nb, (nr % SPL) * 640, (tc + 1) & 1);
                    prefetchQ(nb, (nr / SPL) * 128);
                    asm volatile("cp.async.commit_group;" ::: "memory");
                }
            }

            const char* bb = smem + (tc & 1) * KBUF;
            const char* vb0 = bb + 8192;

            // ---- S = Q K^T (bf16x3), acc pre-init to -bound ----
            float sc[8][4];
            #pragma unroll
            for (int j = 0; j < 8; j++) {
                sc[j][0] = -bd0; sc[j][1] = -bd0;
                sc[j][2] = -bd1; sc[j][3] = -bd1;
            }
            #pragma unroll
            for (int s = 0; s < 2; s++) {
                const int so = (((s ^ gp) << 2) + t4) << 4;
                #pragma unroll
                for (int j = 0; j < 8; j++) {
                    uint4 kk = *(const uint4*)(bb + ((8 * j + g) << 7) + so);
                    mma_bf16(sc[j], ah[s], kk.x, kk.y);
                    mma_bf16(sc[j], al[s], kk.x, kk.y);
                    mma_bf16(sc[j], ah[s], kk.z, kk.w);
                }
            }

            // ---- exp2 -> P fragments ----
            u32 ph[4][4], pl[4][4];
            #pragma unroll
            for (int j = 0; j < 8; j++) {
                float p0 = ex2f(sc[j][0]);
                float p1 = ex2f(sc[j][1]);
                float p2 = ex2f(sc[j][2]);
                float p3 = ex2f(sc[j][3]);
                l0 += p0 + p1; l1 += p2 + p3;
                u32 h01 = pkbf(p1, p0), h23 = pkbf(p3, p2);
                u32 lo01 = pkbf(p1 - bfhi(h01), p0 - bflo(h01));
                u32 lo23 = pkbf(p3 - bfhi(h23), p2 - bflo(h23));
                const int s4 = j >> 1, hf = j & 1;
                ph[s4][2 * hf] = h01; ph[s4][2 * hf + 1] = h23;
                pl[s4][2 * hf] = lo01; pl[s4][2 * hf + 1] = lo23;
            }

            // ---- O += P V (bf16x3) ----
            #pragma unroll
            for (int s4 = 0; s4 < 4; s4++) {
                const int so = (((s4 ^ gp) << 2) + t4) << 4;
                #pragma unroll
                for (int j2 = 0; j2 < 4; j2++) {
                    uint4 vv = *(const uint4*)(vb0 + ((8 * j2 + g) << 8) + so);
                    mma_bf16(o[j2], ph[s4], vv.x, vv.y);
                    mma_bf16(o[j2], pl[s4], vv.x, vv.y);
                    mma_bf16(o[j2], ph[s4], vv.z, vv.w);
                }
            }
            tc++;
        }

        l0 += __shfl_xor_sync(0xffffffffu, l0, 1);
        l0 += __shfl_xor_sync(0xffffffffu, l0, 2);
        l1 += __shfl_xor_sync(0xffffffffu, l1, 1);
        l1 += __shfl_xor_sync(0xffffffffu, l1, 2);

        const int pb = (b * SPL + sp) * NP;
        #pragma unroll
        for (int j2 = 0; j2 < 4; j2++) {
            *(float2*)(g_acc + (pb + q0) * DI + 8 * j2 + 2 * t4) = make_float2(o[j2][0], o[j2][1]);
            *(float2*)(g_acc + (pb + q1) * DI + 8 * j2 + 2 * t4) = make_float2(o[j2][2], o[j2][3]);
        }
        if (t4 == 0) { g_lp[pb + q0] = l0; g_lp[pb + q1] = l1; }

        wi = nwi;
    }
}

// ---------------------------------------------------------------------------
// Stage 3: merge SPL partials + output projection + residual.
// ---------------------------------------------------------------------------
__global__ void __launch_bounds__(128) merge_kernel(
    const float* __restrict__ x,
    const float* __restrict__ w_w,
    float* __restrict__ out)
{
    __shared__ __align__(16) float ws[CH * DI];
    const int b = blockIdx.y, tid = threadIdx.x;
    const int n = blockIdx.x * 128 + tid;

    for (int i = tid; i < CH * DI; i += 128) ws[i] = w_w[i];
    __syncthreads();

    float l = 0.f;
    u64 y2[16];
    #pragma unroll
    for (int i = 0; i < 16; i++) y2[i] = 0ull;
    #pragma unroll 2
    for (int s = 0; s < SPL; s++) {
        l += g_lp[(b * SPL + s) * NP + n];
        const u64* ap = (const u64*)(g_acc + ((b * SPL + s) * NP + n) * DI);
        #pragma unroll
        for (int i2 = 0; i2 < 16; i2++) y2[i2] = f2add(y2[i2], ap[i2]);
    }
    const float inv = 1.f / l;
    u64 inv2; asm("mov.b64 %0,{%1,%1};" : "=l"(inv2) : "f"(inv));
    #pragma unroll
    for (int i2 = 0; i2 < 16; i2++) {
        u64 z = 0ull;
        y2[i2] = f2fma(y2[i2], inv2, z);
    }

    const float* xb = x + b * CH * NP + n;
    float* ob = out + b * CH * NP + n;
    #pragma unroll 2
    for (int c = 0; c < CH; c++) {
        const u64* w2 = (const u64*)(ws + c * DI);
        u64 o2 = 0ull;
        #pragma unroll
        for (int i2 = 0; i2 < 16; i2++) o2 = f2fma(w2[i2], y2[i2], o2);
        ob[c * NP] = xb[c * NP] + f2hadd(o2);
    }
}

// ---------------------------------------------------------------------------
extern "C" void kernel_launch(void* const* d_in, const int* in_sizes, int n_in,
                              void* d_out, int out_size)
{
    const float* x       = (const float*)d_in[0];
    const float* gw      = (const float*)d_in[1];
    const float* theta_w = (const float*)d_in[2];
    const float* phi_w   = (const float*)d_in[3];
    const float* w_w     = (const float*)d_in[4];
    float* out           = (float*)d_out;

    void* pm = nullptr; cudaGetSymbolAddress(&pm, g_phimax);
    cudaMemsetAsync(pm, 0, sizeof(unsigned) * BATCH);
    void* pc = nullptr; cudaGetSymbolAddress(&pc, g_ctr);
    cudaMemsetAsync(pc, 0, sizeof(unsigned));

    static int cfg = 0;
    if (!cfg) {
        cudaFuncSetAttribute(attn_kernel, cudaFuncAttributeMaxDynamicSharedMemorySize, ASMEM);
        cfg = 1;
    }

    dim3 gp(NP / 128, 3, BATCH);
    proj_kernel<<<gp, 128>>>(x, theta_w, phi_w, gw);

    attn_kernel<<<296, 256, ASMEM>>>();

    dim3 gm(NP / 128, BATCH);
    merge_kernel<<<gm, 128>>>(x, w_w, out);
}

// round 10
// speedup vs baseline: 1.0835x; 1.0341x over previous
#include <cuda_runtime.h>
#include <cuda_bf16.h>
#include <cstdint>

#define BATCH 2
#define CH 64
#define DI 32
#define NP 6400
#define SPL 10
#define QTCH 100               // 64-key chunks per batch (g_Vz stride)
#define TPI 10                 // tiles per item (640 keys)
#define ITEMS 1000             // 2 b * 50 qtiles(128) * 10 splits
#define LOG2E 1.4426950408889634f

typedef uint32_t u32;
typedef unsigned long long u64;

// ---------------- scratch ----------------
__device__ __nv_bfloat16 g_Qh[BATCH * NP * DI], g_Ql[BATCH * NP * DI];
__device__ uint4 g_Kz[BATCH * NP * 8];
__device__ uint4 g_Vz[BATCH * DI * QTCH * 16];
__device__ float g_thn[BATCH * NP];
__device__ unsigned g_phimax[BATCH];
__device__ unsigned g_ctr;
__device__ float g_acc[BATCH * SPL * NP * DI];
__device__ float g_lp[BATCH * SPL * NP];

// ---------------- helpers ----------------
__device__ __forceinline__ u64 f2fma(u64 a, u64 b, u64 c) {
    u64 d; asm("fma.rn.f32x2 %0,%1,%2,%3;" : "=l"(d) : "l"(a), "l"(b), "l"(c)); return d;
}
__device__ __forceinline__ u64 f2add(u64 a, u64 b) {
    u64 d; asm("add.rn.f32x2 %0,%1,%2;" : "=l"(d) : "l"(a), "l"(b)); return d;
}
__device__ __forceinline__ float f2hadd(u64 a) {
    float lo, hi; asm("mov.b64 {%0,%1},%2;" : "=f"(lo), "=f"(hi) : "l"(a)); return lo + hi;
}
__device__ __forceinline__ u32 pkbf(float hi, float lo) {
    u32 r; asm("cvt.rn.bf16x2.f32 %0,%1,%2;" : "=r"(r) : "f"(hi), "f"(lo)); return r;
}
__device__ __forceinline__ float bflo(u32 p) { return __uint_as_float(p << 16); }
__device__ __forceinline__ float bfhi(u32 p) { return __uint_as_float(p & 0xffff0000u); }
__device__ __forceinline__ float ex2f(float x) {
    float r; asm("ex2.approx.f32 %0,%1;" : "=f"(r) : "f"(x)); return r;
}
__device__ __forceinline__ void mma_bf16(float* c, const u32* a, u32 b0, u32 b1) {
    asm("mma.sync.aligned.m16n8k16.row.col.f32.bf16.bf16.f32 "
        "{%0,%1,%2,%3},{%4,%5,%6,%7},{%8,%9},{%0,%1,%2,%3};"
        : "+f"(c[0]), "+f"(c[1]), "+f"(c[2]), "+f"(c[3])
        : "r"(a[0]), "r"(a[1]), "r"(a[2]), "r"(a[3]), "r"(b0), "r"(b1));
}
__device__ __forceinline__ void cpa16(u32 sa, const void* g) {
    asm volatile("cp.async.cg.shared.global [%0],[%1],16;" :: "r"(sa), "l"(g) : "memory");
}
__device__ __forceinline__ u32 smaddr(const void* p) {
    u32 a; asm("{ .reg .u64 t; cvta.to.shared.u64 t,%1; cvt.u32.u64 %0,t; }" : "=r"(a) : "l"(p));
    return a;
}

// ---------------------------------------------------------------------------
// Stage 1: projection. grid (100, 3, 2), 128 threads; 2 threads per position
// (h = tid&1 owns outputs 16h..16h+15), 64 positions per CTA.
// m=0: theta(*log2e) -> Qh/Ql + thn; m=1: phi -> swizzled g_Kz + phimax;
// m=2: g -> swizzled transposed g_Vz.
// ---------------------------------------------------------------------------
#define PQ 64
__global__ void __launch_bounds__(128) proj_kernel(
    const float* __restrict__ x,
    const float* __restrict__ theta_w,
    const float* __restrict__ phi_w,
    const float* __restrict__ gw)
{
    __shared__ __align__(16) float xs[CH * PQ];     // 16KB (reused for V staging)
    __shared__ __align__(16) float wT[CH * DI];     // 8KB

    const int b = blockIdx.z, m = blockIdx.y, n0 = blockIdx.x * PQ;
    const int tid = threadIdx.x;
    const int p = tid >> 1, h = tid & 1;
    const float* wsrc = (m == 0) ? theta_w : (m == 1) ? phi_w : gw;

    for (int idx = tid; idx < DI * CH; idx += 128) {
        int i = idx >> 6, c = idx & 63;
        wT[c * DI + i] = wsrc[idx];
    }
    const float* xb = x + b * CH * NP + n0;
    #pragma unroll
    for (int i = 0; i < 32; i++) {
        int idx = tid + 128 * i;
        xs[idx] = xb[(idx >> 6) * NP + (idx & 63)];
    }
    __syncthreads();

    u64 acc2[8];
    #pragma unroll
    for (int i = 0; i < 8; i++) acc2[i] = 0ull;
    #pragma unroll 4
    for (int c = 0; c < CH; c++) {
        float xv = xs[c * PQ + p];
        u64 x2; asm("mov.b64 %0,{%1,%1};" : "=l"(x2) : "f"(xv));
        const ulonglong2* w2 = (const ulonglong2*)(wT + c * DI + 16 * h);
        #pragma unroll
        for (int i4 = 0; i4 < 4; i4++) {
            ulonglong2 ww = w2[i4];
            acc2[2 * i4]     = f2fma(ww.x, x2, acc2[2 * i4]);
            acc2[2 * i4 + 1] = f2fma(ww.y, x2, acc2[2 * i4 + 1]);
        }
    }
    float v[16];
    #pragma unroll
    for (int i2 = 0; i2 < 8; i2++)
        asm("mov.b64 {%0,%1},%2;" : "=f"(v[2 * i2]), "=f"(v[2 * i2 + 1]) : "l"(acc2[i2]));

    const int n = n0 + p;
    if (m == 0) {
        #pragma unroll
        for (int i = 0; i < 16; i++) v[i] *= LOG2E;
        float nrm = 0.f;
        u32 hb[8], lb[8];
        #pragma unroll
        for (int i2 = 0; i2 < 8; i2++) {
            float f0 = v[2 * i2], f1 = v[2 * i2 + 1];
            nrm = fmaf(f0, f0, fmaf(f1, f1, nrm));
            u32 hh = pkbf(f1, f0);
            hb[i2] = hh;
            lb[i2] = pkbf(f1 - bfhi(hh), f0 - bflo(hh));
        }
        nrm += __shfl_xor_sync(0xffffffffu, nrm, 1);
        uint4* hp = (uint4*)((u32*)g_Qh + (b * NP + n) * 16 + 8 * h);
        uint4* lp = (uint4*)((u32*)g_Ql + (b * NP + n) * 16 + 8 * h);
        hp[0] = make_uint4(hb[0], hb[1], hb[2], hb[3]);
        hp[1] = make_uint4(hb[4], hb[5], hb[6], hb[7]);
        lp[0] = make_uint4(lb[0], lb[1], lb[2], lb[3]);
        lp[1] = make_uint4(lb[4], lb[5], lb[6], lb[7]);
        if (h == 0) g_thn[b * NP + n] = nrm;
    } else if (m == 1) {
        float nrm = 0.f;
        u32 hb[8], lb[8];
        #pragma unroll
        for (int i2 = 0; i2 < 8; i2++) {
            float f0 = v[2 * i2], f1 = v[2 * i2 + 1];
            nrm = fmaf(f0, f0, fmaf(f1, f1, nrm));
            u32 hh = pkbf(f1, f0);
            hb[i2] = hh;
            lb[i2] = pkbf(f1 - bfhi(hh), f0 - bflo(hh));
        }
        nrm += __shfl_xor_sync(0xffffffffu, nrm, 1);
        uint4* dst = (uint4*)g_Kz + (b * NP + n) * 8;
        #pragma unroll
        for (int t4 = 0; t4 < 4; t4++) {
            int blk = ((h ^ (n & 1)) << 2) + t4;
            dst[blk] = make_uint4(hb[t4], hb[4 + t4], lb[t4], lb[4 + t4]);
        }
        unsigned mx = __reduce_max_sync(0xffffffffu, __float_as_uint(nrm));
        if ((tid & 31) == 0) atomicMax(&g_phimax[b], mx);
    } else {
        __syncthreads();       // all xs reads done
        u32* vh = (u32*)xs;    // [32 dims][32 u32-pairs of 64 keys]
        u32* vl = vh + 32 * 32;
        __nv_bfloat16* vhb = (__nv_bfloat16*)vh;
        __nv_bfloat16* vlb = (__nv_bfloat16*)vl;
        #pragma unroll
        for (int i = 0; i < 16; i++) {
            int d = 16 * h + i;
            __nv_bfloat16 hh = __float2bfloat16(v[i]);
            vhb[d * PQ + p] = hh;
            vlb[d * PQ + p] = __float2bfloat16(v[i] - __bfloat162float(hh));
        }
        __syncthreads();
        #pragma unroll
        for (int i = 0; i < 4; i++) {
            int idx = tid + 128 * i;     // 512 blocks
            int d = idx >> 4, rem = idx & 15;
            int s4 = rem >> 2, t4 = rem & 3;
            int kp = 8 * s4 + t4;
            uint4 val = make_uint4(vh[d * 32 + kp], vh[d * 32 + kp + 4],
                                   vl[d * 32 + kp], vl[d * 32 + kp + 4]);
            int blk = ((s4 ^ (d & 1)) << 2) + t4;
            g_Vz[((b * DI + d) * QTCH + blockIdx.x) * 16 + blk] = val;
        }
    }
}

// ---------------------------------------------------------------------------
// Stage 2: pipelined persistent flash attention, j-pair software pipeline so
// exp/pack (MUFU/ALU) overlaps MMA (tensor) inside each warp's stream.
// 296 CTAs x 256 thr. item = (b, 128-query tile, 640-key split).
// ---------------------------------------------------------------------------
#define KBUF 16384
#define QOFF 32768
#define SMN  49152
#define ASMEM 49168

__global__ void __launch_bounds__(256, 2) attn_kernel()
{
    extern __shared__ __align__(16) char smem[];
    const int tid = threadIdx.x, w = tid >> 5, lane = tid & 31;
    const int g = lane >> 2, t4 = lane & 3;
    const int gp = g & 1;
    const u32 smbase = smaddr(smem);
    volatile u32* sm_next = (volatile u32*)(smem + SMN);

    auto prefetchKV = [&](int b, int k0, int buf) {
        const u32 bb = smbase + buf * KBUF;
        const uint4* ks = g_Kz + (b * NP + k0) * 8;
        const uint4* vs = g_Vz + (b * DI * QTCH + (k0 >> 6)) * 16;
        #pragma unroll
        for (int i = 0; i < 2; i++) {
            int idx = tid + 256 * i;
            cpa16(bb + idx * 16, ks + idx);
            int d = idx >> 4, blk = idx & 15;
            cpa16(bb + 8192 + idx * 16, vs + d * QTCH * 16 + blk);
        }
    };
    auto prefetchQ = [&](int b, int n0) {
        const uint4* qh = (const uint4*)(g_Qh + (b * NP + n0) * DI);
        const uint4* ql = (const uint4*)(g_Ql + (b * NP + n0) * DI);
        #pragma unroll
        for (int i = 0; i < 2; i++) {
            int idx = tid + 256 * i;
            cpa16(smbase + QOFF + idx * 16, qh + idx);
            cpa16(smbase + QOFF + 8192 + idx * 16, ql + idx);
        }
    };

    if (tid == 0) *sm_next = atomicAdd(&g_ctr, 1u);
    __syncthreads();
    unsigned wi = *sm_next;
    if (wi < ITEMS) {
        int b = wi / 500, r = wi % 500;
        prefetchKV(b, (r % SPL) * 640, 0);
        prefetchQ(b, (r / SPL) * 128);
        asm volatile("cp.async.commit_group;" ::: "memory");
    }
    int tc = 0;

    while (wi < ITEMS) {
        const int b = wi / 500;
        const int r = wi % 500;
        const int qt = r / SPL, sp = r % SPL;
        const int n0 = qt * 128, k0s = sp * 640;
        const int lr0 = w * 16 + g;
        const int q0 = n0 + lr0, q1 = q0 + 8;

        const float pm = sqrtf(__uint_as_float(g_phimax[b]));
        const float bd0 = sqrtf(g_thn[b * NP + q0]) * pm;
        const float bd1 = sqrtf(g_thn[b * NP + q1]) * pm;

        float o[4][4];
        #pragma unroll
        for (int i = 0; i < 4; i++)
            #pragma unroll
            for (int j = 0; j < 4; j++) o[i][j] = 0.f;
        float l0 = 0.f, l1 = 0.f;
        u32 ah[2][4], al[2][4];
        unsigned nwi = ITEMS;

        for (int t = 0; t < TPI; t++) {
            asm volatile("cp.async.wait_group 0;" ::: "memory");
            __syncthreads();

            if (t == 0) {
                const u32* qh32 = (const u32*)(smem + QOFF);
                const u32* ql32 = (const u32*)(smem + QOFF + 8192);
                const int r0 = lr0 * 16, r1 = (lr0 + 8) * 16;
                #pragma unroll
                for (int s = 0; s < 2; s++) {
                    ah[s][0] = qh32[r0 + t4 + 8 * s];
                    ah[s][1] = qh32[r1 + t4 + 8 * s];
                    ah[s][2] = qh32[r0 + t4 + 4 + 8 * s];
                    ah[s][3] = qh32[r1 + t4 + 4 + 8 * s];
                    al[s][0] = ql32[r0 + t4 + 8 * s];
                    al[s][1] = ql32[r1 + t4 + 8 * s];
                    al[s][2] = ql32[r0 + t4 + 4 + 8 * s];
                    al[s][3] = ql32[r1 + t4 + 4 + 8 * s];
                }
            }
            if (t == TPI - 2 && tid == 0) *sm_next = atomicAdd(&g_ctr, 1u);
            if (t < TPI - 1) {
                prefetchKV(b, k0s + (t + 1) * 64, (tc + 1) & 1);
                asm volatile("cp.async.commit_group;" ::: "memory");
            } else {
                nwi = *sm_next;
                if (nwi < ITEMS) {
                    int nb = nwi / 500, nr = nwi % 500;
                    prefetchKV(nb, (nr % SPL) * 640, (tc + 1) & 1);
                    prefetchQ(nb, (nr / SPL) * 128);
                    asm volatile("cp.async.commit_group;" ::: "memory");
                }
            }

            const char* bb = smem + (tc & 1) * KBUF;
            const char* vb0 = bb + 8192;

            // ---- j-pair software pipeline: QK(jp+1) | exp/pack(jp) | PV(jp) ----
            float sc[2][2][4];
            u32 ph[4], pl[4];

            // QK for pair jp into scp (2 rows of 8 keys), acc pre-init to -bound
            #define QK_PAIR(jp, scp)                                            \
                do {                                                            \
                    (scp)[0][0] = -bd0; (scp)[0][1] = -bd0;                     \
                    (scp)[0][2] = -bd1; (scp)[0][3] = -bd1;                     \
                    (scp)[1][0] = -bd0; (scp)[1][1] = -bd0;                     \
                    (scp)[1][2] = -bd1; (scp)[1][3] = -bd1;                     \
                    _Pragma("unroll")                                           \
                    for (int s = 0; s < 2; s++) {                               \
                        const int so = (((s ^ gp) << 2) + t4) << 4;             \
                        _Pragma("unroll")                                       \
                        for (int jj = 0; jj < 2; jj++) {                        \
                            int j = 2 * (jp) + jj;                              \
                            uint4 kk = *(const uint4*)(bb + ((8 * j + g) << 7) + so); \
                            mma_bf16((scp)[jj], ah[s], kk.x, kk.y);             \
                            mma_bf16((scp)[jj], al[s], kk.x, kk.y);             \
                            mma_bf16((scp)[jj], ah[s], kk.z, kk.w);             \
                        }                                                       \
                    }                                                           \
                } while (0)

            QK_PAIR(0, sc[0]);
            #pragma unroll
            for (int jp = 0; jp < 4; jp++) {
                if (jp < 3) QK_PAIR(jp + 1, sc[(jp + 1) & 1]);

                float* s0 = sc[jp & 1][0];
                float* s1 = sc[jp & 1][1];
                float p0 = ex2f(s0[0]), p1 = ex2f(s0[1]);
                float p2 = ex2f(s0[2]), p3 = ex2f(s0[3]);
                float p4 = ex2f(s1[0]), p5 = ex2f(s1[1]);
                float p6 = ex2f(s1[2]), p7 = ex2f(s1[3]);
                l0 += p0 + p1 + p4 + p5;
                l1 += p2 + p3 + p6 + p7;
                u32 h01 = pkbf(p1, p0), h23 = pkbf(p3, p2);
                u32 h45 = pkbf(p5, p4), h67 = pkbf(p7, p6);
                ph[0] = h01; ph[1] = h23; ph[2] = h45; ph[3] = h67;
                pl[0] = pkbf(p1 - bfhi(h01), p0 - bflo(h01));
                pl[1] = pkbf(p3 - bfhi(h23), p2 - bflo(h23));
                pl[2] = pkbf(p5 - bfhi(h45), p4 - bflo(h45));
                pl[3] = pkbf(p7 - bfhi(h67), p6 - bflo(h67));

                const int so4 = (((jp ^ gp) << 2) + t4) << 4;
                #pragma unroll
                for (int j2 = 0; j2 < 4; j2++) {
                    uint4 vv = *(const uint4*)(vb0 + ((8 * j2 + g) << 8) + so4);
                    mma_bf16(o[j2], ph, vv.x, vv.y);
                    mma_bf16(o[j2], pl, vv.x, vv.y);
                    mma_bf16(o[j2], ph, vv.z, vv.w);
                }
            }
            #undef QK_PAIR
            tc++;
        }

        l0 += __shfl_xor_sync(0xffffffffu, l0, 1);
        l0 += __shfl_xor_sync(0xffffffffu, l0, 2);
        l1 += __shfl_xor_sync(0xffffffffu, l1, 1);
        l1 += __shfl_xor_sync(0xffffffffu, l1, 2);

        const int pb = (b * SPL + sp) * NP;
        #pragma unroll
        for (int j2 = 0; j2 < 4; j2++) {
            *(float2*)(g_acc + (pb + q0) * DI + 8 * j2 + 2 * t4) = make_float2(o[j2][0], o[j2][1]);
            *(float2*)(g_acc + (pb + q1) * DI + 8 * j2 + 2 * t4) = make_float2(o[j2][2], o[j2][3]);
        }
        if (t4 == 0) { g_lp[pb + q0] = l0; g_lp[pb + q1] = l1; }

        wi = nwi;
    }
}

// ---------------------------------------------------------------------------
// Stage 3: merge SPL partials + output projection + residual.
// ---------------------------------------------------------------------------
__global__ void __launch_bounds__(128) merge_kernel(
    const float* __restrict__ x,
    const float* __restrict__ w_w,
    float* __restrict__ out)
{
    __shared__ __align__(16) float ws[CH * DI];
    const int b = blockIdx.y, tid = threadIdx.x;
    const int n = blockIdx.x * 128 + tid;

    for (int i = tid; i < CH * DI; i += 128) ws[i] = w_w[i];
    __syncthreads();

    float l = 0.f;
    u64 y2[16];
    #pragma unroll
    for (int i = 0; i < 16; i++) y2[i] = 0ull;
    #pragma unroll 2
    for (int s = 0; s < SPL; s++) {
        l += g_lp[(b * SPL + s) * NP + n];
        const u64* ap = (const u64*)(g_acc + ((b * SPL + s) * NP + n) * DI);
        #pragma unroll
        for (int i2 = 0; i2 < 16; i2++) y2[i2] = f2add(y2[i2], ap[i2]);
    }
    const float inv = 1.f / l;
    u64 inv2; asm("mov.b64 %0,{%1,%1};" : "=l"(inv2) : "f"(inv));
    #pragma unroll
    for (int i2 = 0; i2 < 16; i2++) {
        u64 z = 0ull;
        y2[i2] = f2fma(y2[i2], inv2, z);
    }

    const float* xb = x + b * CH * NP + n;
    float* ob = out + b * CH * NP + n;
    #pragma unroll 2
    for (int c = 0; c < CH; c++) {
        const u64* w2 = (const u64*)(ws + c * DI);
        u64 o2 = 0ull;
        #pragma unroll
        for (int i2 = 0; i2 < 16; i2++) o2 = f2fma(w2[i2], y2[i2], o2);
        ob[c * NP] = xb[c * NP] + f2hadd(o2);
    }
}

// ---------------------------------------------------------------------------
extern "C" void kernel_launch(void* const* d_in, const int* in_sizes, int n_in,
                              void* d_out, int out_size)
{
    const float* x       = (const float*)d_in[0];
    const float* gw      = (const float*)d_in[1];
    const float* theta_w = (const float*)d_in[2];
    const float* phi_w   = (const float*)d_in[3];
    const float* w_w     = (const float*)d_in[4];
    float* out           = (float*)d_out;

    void* pm = nullptr; cudaGetSymbolAddress(&pm, g_phimax);
    cudaMemsetAsync(pm, 0, sizeof(unsigned) * BATCH);
    void* pc = nullptr; cudaGetSymbolAddress(&pc, g_ctr);
    cudaMemsetAsync(pc, 0, sizeof(unsigned));

    static int cfg = 0;
    if (!cfg) {
        cudaFuncSetAttribute(attn_kernel, cudaFuncAttributeMaxDynamicSharedMemorySize, ASMEM);
        cfg = 1;
    }

    dim3 gp(NP / PQ, 3, BATCH);
    proj_kernel<<<gp, 128>>>(x, theta_w, phi_w, gw);

    attn_kernel<<<296, 256, ASMEM>>>();

    dim3 gm(NP / 128, BATCH);
    merge_kernel<<<gm, 128>>>(x, w_w, out);
}

// round 11
// speedup vs baseline: 1.2044x; 1.1116x over previous
#include <cuda_runtime.h>
#include <cuda_bf16.h>
#include <cstdint>

#define BATCH 2
#define CH 64
#define DI 32
#define NP 6400
#define SPL 10
#define QTCH 100               // 64-key chunks per batch (g_Vz stride)
#define TPI 10                 // tiles per item (640 keys)
#define ITEMS 1000             // 2 b * 50 qtiles(128) * 10 splits
#define LOG2E 1.4426950408889634f

typedef uint32_t u32;
typedef unsigned long long u64;

// ---------------- scratch ----------------
__device__ __nv_bfloat16 g_Qh[BATCH * NP * DI], g_Ql[BATCH * NP * DI];
__device__ uint4 g_Kz[BATCH * NP * 8];
__device__ uint4 g_Vz[BATCH * DI * QTCH * 16];
__device__ float g_thn[BATCH * NP];
__device__ unsigned g_phimax[BATCH];
__device__ unsigned g_ctr;
__device__ float g_acc[BATCH * SPL * NP * DI];
__device__ float g_lp[BATCH * SPL * NP];

// ---------------- helpers ----------------
__device__ __forceinline__ u64 f2fma(u64 a, u64 b, u64 c) {
    u64 d; asm("fma.rn.f32x2 %0,%1,%2,%3;" : "=l"(d) : "l"(a), "l"(b), "l"(c)); return d;
}
__device__ __forceinline__ u64 f2add(u64 a, u64 b) {
    u64 d; asm("add.rn.f32x2 %0,%1,%2;" : "=l"(d) : "l"(a), "l"(b)); return d;
}
__device__ __forceinline__ float f2hadd(u64 a) {
    float lo, hi; asm("mov.b64 {%0,%1},%2;" : "=f"(lo), "=f"(hi) : "l"(a)); return lo + hi;
}
__device__ __forceinline__ u32 pkbf(float hi, float lo) {
    u32 r; asm("cvt.rn.bf16x2.f32 %0,%1,%2;" : "=r"(r) : "f"(hi), "f"(lo)); return r;
}
__device__ __forceinline__ float bflo(u32 p) { return __uint_as_float(p << 16); }
__device__ __forceinline__ float bfhi(u32 p) { return __uint_as_float(p & 0xffff0000u); }
__device__ __forceinline__ float ex2f(float x) {
    float r; asm("ex2.approx.f32 %0,%1;" : "=f"(r) : "f"(x)); return r;
}
__device__ __forceinline__ void mma_bf16(float* c, const u32* a, u32 b0, u32 b1) {
    asm("mma.sync.aligned.m16n8k16.row.col.f32.bf16.bf16.f32 "
        "{%0,%1,%2,%3},{%4,%5,%6,%7},{%8,%9},{%0,%1,%2,%3};"
        : "+f"(c[0]), "+f"(c[1]), "+f"(c[2]), "+f"(c[3])
        : "r"(a[0]), "r"(a[1]), "r"(a[2]), "r"(a[3]), "r"(b0), "r"(b1));
}
__device__ __forceinline__ void cpa16(u32 sa, const void* g) {
    asm volatile("cp.async.cg.shared.global [%0],[%1],16;" :: "r"(sa), "l"(g) : "memory");
}
__device__ __forceinline__ u32 smaddr(const void* p) {
    u32 a; asm("{ .reg .u64 t; cvta.to.shared.u64 t,%1; cvt.u32.u64 %0,t; }" : "=r"(a) : "l"(p));
    return a;
}

// ---------------------------------------------------------------------------
// Stage 1: projection. grid (100, 3, 2), 128 threads; 2 threads per position
// (h = tid&1 owns outputs 16h..16h+15), 64 positions per CTA.
// ---------------------------------------------------------------------------
#define PQ 64
__global__ void __launch_bounds__(128) proj_kernel(
    const float* __restrict__ x,
    const float* __restrict__ theta_w,
    const float* __restrict__ phi_w,
    const float* __restrict__ gw)
{
    __shared__ __align__(16) float xs[CH * PQ];     // 16KB (reused for V staging)
    __shared__ __align__(16) float wT[CH * DI];     // 8KB

    const int b = blockIdx.z, m = blockIdx.y, n0 = blockIdx.x * PQ;
    const int tid = threadIdx.x;
    const int p = tid >> 1, h = tid & 1;
    const float* wsrc = (m == 0) ? theta_w : (m == 1) ? phi_w : gw;

    for (int idx = tid; idx < DI * CH; idx += 128) {
        int i = idx >> 6, c = idx & 63;
        wT[c * DI + i] = wsrc[idx];
    }
    const float* xb = x + b * CH * NP + n0;
    #pragma unroll
    for (int i = 0; i < 32; i++) {
        int idx = tid + 128 * i;
        xs[idx] = xb[(idx >> 6) * NP + (idx & 63)];
    }
    __syncthreads();

    u64 acc2[8];
    #pragma unroll
    for (int i = 0; i < 8; i++) acc2[i] = 0ull;
    #pragma unroll 4
    for (int c = 0; c < CH; c++) {
        float xv = xs[c * PQ + p];
        u64 x2; asm("mov.b64 %0,{%1,%1};" : "=l"(x2) : "f"(xv));
        const ulonglong2* w2 = (const ulonglong2*)(wT + c * DI + 16 * h);
        #pragma unroll
        for (int i4 = 0; i4 < 4; i4++) {
            ulonglong2 ww = w2[i4];
            acc2[2 * i4]     = f2fma(ww.x, x2, acc2[2 * i4]);
            acc2[2 * i4 + 1] = f2fma(ww.y, x2, acc2[2 * i4 + 1]);
        }
    }
    float v[16];
    #pragma unroll
    for (int i2 = 0; i2 < 8; i2++)
        asm("mov.b64 {%0,%1},%2;" : "=f"(v[2 * i2]), "=f"(v[2 * i2 + 1]) : "l"(acc2[i2]));

    const int n = n0 + p;
    if (m == 0) {
        #pragma unroll
        for (int i = 0; i < 16; i++) v[i] *= LOG2E;
        float nrm = 0.f;
        u32 hb[8], lb[8];
        #pragma unroll
        for (int i2 = 0; i2 < 8; i2++) {
            float f0 = v[2 * i2], f1 = v[2 * i2 + 1];
            nrm = fmaf(f0, f0, fmaf(f1, f1, nrm));
            u32 hh = pkbf(f1, f0);
            hb[i2] = hh;
            lb[i2] = pkbf(f1 - bfhi(hh), f0 - bflo(hh));
        }
        nrm += __shfl_xor_sync(0xffffffffu, nrm, 1);
        uint4* hp = (uint4*)((u32*)g_Qh + (b * NP + n) * 16 + 8 * h);
        uint4* lp = (uint4*)((u32*)g_Ql + (b * NP + n) * 16 + 8 * h);
        hp[0] = make_uint4(hb[0], hb[1], hb[2], hb[3]);
        hp[1] = make_uint4(hb[4], hb[5], hb[6], hb[7]);
        lp[0] = make_uint4(lb[0], lb[1], lb[2], lb[3]);
        lp[1] = make_uint4(lb[4], lb[5], lb[6], lb[7]);
        if (h == 0) g_thn[b * NP + n] = nrm;
    } else if (m == 1) {
        float nrm = 0.f;
        u32 hb[8], lb[8];
        #pragma unroll
        for (int i2 = 0; i2 < 8; i2++) {
            float f0 = v[2 * i2], f1 = v[2 * i2 + 1];
            nrm = fmaf(f0, f0, fmaf(f1, f1, nrm));
            u32 hh = pkbf(f1, f0);
            hb[i2] = hh;
            lb[i2] = pkbf(f1 - bfhi(hh), f0 - bflo(hh));
        }
        nrm += __shfl_xor_sync(0xffffffffu, nrm, 1);
        uint4* dst = (uint4*)g_Kz + (b * NP + n) * 8;
        #pragma unroll
        for (int t4 = 0; t4 < 4; t4++) {
            int blk = ((h ^ (n & 1)) << 2) + t4;
            dst[blk] = make_uint4(hb[t4], hb[4 + t4], lb[t4], lb[4 + t4]);
        }
        unsigned mx = __reduce_max_sync(0xffffffffu, __float_as_uint(nrm));
        if ((tid & 31) == 0) atomicMax(&g_phimax[b], mx);
    } else {
        __syncthreads();       // all xs reads done
        u32* vh = (u32*)xs;    // [32 dims][32 u32-pairs of 64 keys]
        u32* vl = vh + 32 * 32;
        __nv_bfloat16* vhb = (__nv_bfloat16*)vh;
        __nv_bfloat16* vlb = (__nv_bfloat16*)vl;
        #pragma unroll
        for (int i = 0; i < 16; i++) {
            int d = 16 * h + i;
            __nv_bfloat16 hh = __float2bfloat16(v[i]);
            vhb[d * PQ + p] = hh;
            vlb[d * PQ + p] = __float2bfloat16(v[i] - __bfloat162float(hh));
        }
        __syncthreads();
        #pragma unroll
        for (int i = 0; i < 4; i++) {
            int idx = tid + 128 * i;     // 512 blocks
            int d = idx >> 4, rem = idx & 15;
            int s4 = rem >> 2, t4 = rem & 3;
            int kp = 8 * s4 + t4;
            uint4 val = make_uint4(vh[d * 32 + kp], vh[d * 32 + kp + 4],
                                   vl[d * 32 + kp], vl[d * 32 + kp + 4]);
            int blk = ((s4 ^ (d & 1)) << 2) + t4;
            g_Vz[((b * DI + d) * QTCH + blockIdx.x) * 16 + blk] = val;
        }
    }
}

// ---------------------------------------------------------------------------
// Stage 2: pipelined persistent flash attention. PV uses 2 products
// (Ph*Vh + Ph*Vl) with l accumulated from the bf16-ROUNDED Ph, so the
// normalization cancels the rounding common-mode. 80 MMAs/warp-tile.
// 296 CTAs x 256 thr. item = (b, 128-query tile, 640-key split).
// ---------------------------------------------------------------------------
#define KBUF 16384
#define QOFF 32768
#define SMN  49152
#define ASMEM 49168

__global__ void __launch_bounds__(256, 2) attn_kernel()
{
    extern __shared__ __align__(16) char smem[];
    const int tid = threadIdx.x, w = tid >> 5, lane = tid & 31;
    const int g = lane >> 2, t4 = lane & 3;
    const int gp = g & 1;
    const u32 smbase = smaddr(smem);
    volatile u32* sm_next = (volatile u32*)(smem + SMN);

    auto prefetchKV = [&](int b, int k0, int buf) {
        const u32 bb = smbase + buf * KBUF;
        const uint4* ks = g_Kz + (b * NP + k0) * 8;
        const uint4* vs = g_Vz + (b * DI * QTCH + (k0 >> 6)) * 16;
        #pragma unroll
        for (int i = 0; i < 2; i++) {
            int idx = tid + 256 * i;
            cpa16(bb + idx * 16, ks + idx);
            int d = idx >> 4, blk = idx & 15;
            cpa16(bb + 8192 + idx * 16, vs + d * QTCH * 16 + blk);
        }
    };
    auto prefetchQ = [&](int b, int n0) {
        const uint4* qh = (const uint4*)(g_Qh + (b * NP + n0) * DI);
        const uint4* ql = (const uint4*)(g_Ql + (b * NP + n0) * DI);
        #pragma unroll
        for (int i = 0; i < 2; i++) {
            int idx = tid + 256 * i;
            cpa16(smbase + QOFF + idx * 16, qh + idx);
            cpa16(smbase + QOFF + 8192 + idx * 16, ql + idx);
        }
    };

    if (tid == 0) *sm_next = atomicAdd(&g_ctr, 1u);
    __syncthreads();
    unsigned wi = *sm_next;
    if (wi < ITEMS) {
        int b = wi / 500, r = wi % 500;
        prefetchKV(b, (r % SPL) * 640, 0);
        prefetchQ(b, (r / SPL) * 128);
        asm volatile("cp.async.commit_group;" ::: "memory");
    }
    int tc = 0;

    while (wi < ITEMS) {
        const int b = wi / 500;
        const int r = wi % 500;
        const int qt = r / SPL, sp = r % SPL;
        const int n0 = qt * 128, k0s = sp * 640;
        const int lr0 = w * 16 + g;
        const int q0 = n0 + lr0, q1 = q0 + 8;

        const float pm = sqrtf(__uint_as_float(g_phimax[b]));
        const float bd0 = sqrtf(g_thn[b * NP + q0]) * pm;
        const float bd1 = sqrtf(g_thn[b * NP + q1]) * pm;

        float o[4][4];
        #pragma unroll
        for (int i = 0; i < 4; i++)
            #pragma unroll
            for (int j = 0; j < 4; j++) o[i][j] = 0.f;
        float l0 = 0.f, l1 = 0.f;
        u32 ah[2][4], al[2][4];
        unsigned nwi = ITEMS;

        for (int t = 0; t < TPI; t++) {
            asm volatile("cp.async.wait_group 0;" ::: "memory");
            __syncthreads();

            if (t == 0) {
                const u32* qh32 = (const u32*)(smem + QOFF);
                const u32* ql32 = (const u32*)(smem + QOFF + 8192);
                const int r0 = lr0 * 16, r1 = (lr0 + 8) * 16;
                #pragma unroll
                for (int s = 0; s < 2; s++) {
                    ah[s][0] = qh32[r0 + t4 + 8 * s];
                    ah[s][1] = qh32[r1 + t4 + 8 * s];
                    ah[s][2] = qh32[r0 + t4 + 4 + 8 * s];
                    ah[s][3] = qh32[r1 + t4 + 4 + 8 * s];
                    al[s][0] = ql32[r0 + t4 + 8 * s];
                    al[s][1] = ql32[r1 + t4 + 8 * s];
                    al[s][2] = ql32[r0 + t4 + 4 + 8 * s];
                    al[s][3] = ql32[r1 + t4 + 4 + 8 * s];
                }
            }
            if (t == TPI - 2 && tid == 0) *sm_next = atomicAdd(&g_ctr, 1u);
            if (t < TPI - 1) {
                prefetchKV(b, k0s + (t + 1) * 64, (tc + 1) & 1);
                asm volatile("cp.async.commit_group;" ::: "memory");
            } else {
                nwi = *sm_next;
                if (nwi < ITEMS) {
                    int nb = nwi / 500, nr = nwi % 500;
                    prefetchKV(nb, (nr % SPL) * 640, (tc + 1) & 1);
                    prefetchQ(nb, (nr / SPL) * 128);
                    asm volatile("cp.async.commit_group;" ::: "memory");
                }
            }

            const char* bb = smem + (tc & 1) * KBUF;
            const char* vb0 = bb + 8192;

            // ---- j-pair pipeline: QK(jp+1) | exp/pack(jp) | PV(jp) ----
            float sc[2][2][4];
            u32 ph[4];

            #define QK_PAIR(jp, scp)                                            \
                do {                                                            \
                    (scp)[0][0] = -bd0; (scp)[0][1] = -bd0;                     \
                    (scp)[0][2] = -bd1; (scp)[0][3] = -bd1;                     \
                    (scp)[1][0] = -bd0; (scp)[1][1] = -bd0;                     \
                    (scp)[1][2] = -bd1; (scp)[1][3] = -bd1;                     \
                    _Pragma("unroll")                                           \
                    for (int s = 0; s < 2; s++) {                               \
                        const int so = (((s ^ gp) << 2) + t4) << 4;             \
                        _Pragma("unroll")                                       \
                        for (int jj = 0; jj < 2; jj++) {                        \
                            int j = 2 * (jp) + jj;                              \
                            uint4 kk = *(const uint4*)(bb + ((8 * j + g) << 7) + so); \
                            mma_bf16((scp)[jj], ah[s], kk.x, kk.y);             \
                            mma_bf16((scp)[jj], al[s], kk.x, kk.y);             \
                            mma_bf16((scp)[jj], ah[s], kk.z, kk.w);             \
                        }                                                       \
                    }                                                           \
                } while (0)

            QK_PAIR(0, sc[0]);
            #pragma unroll
            for (int jp = 0; jp < 4; jp++) {
                if (jp < 3) QK_PAIR(jp + 1, sc[(jp + 1) & 1]);

                float* s0 = sc[jp & 1][0];
                float* s1 = sc[jp & 1][1];
                float p0 = ex2f(s0[0]), p1 = ex2f(s0[1]);
                float p2 = ex2f(s0[2]), p3 = ex2f(s0[3]);
                float p4 = ex2f(s1[0]), p5 = ex2f(s1[1]);
                float p6 = ex2f(s1[2]), p7 = ex2f(s1[3]);
                ph[0] = pkbf(p1, p0); ph[1] = pkbf(p3, p2);
                ph[2] = pkbf(p5, p4); ph[3] = pkbf(p7, p6);
                // l from the ROUNDED Ph so normalization cancels rounding
                l0 += bflo(ph[0]) + bfhi(ph[0]) + bflo(ph[2]) + bfhi(ph[2]);
                l1 += bflo(ph[1]) + bfhi(ph[1]) + bflo(ph[3]) + bfhi(ph[3]);

                const int so4 = (((jp ^ gp) << 2) + t4) << 4;
                #pragma unroll
                for (int j2 = 0; j2 < 4; j2++) {
                    uint4 vv = *(const uint4*)(vb0 + ((8 * j2 + g) << 8) + so4);
                    mma_bf16(o[j2], ph, vv.x, vv.y);   // Ph * Vh
                    mma_bf16(o[j2], ph, vv.z, vv.w);   // Ph * Vl
                }
            }
            #undef QK_PAIR
            tc++;
        }

        l0 += __shfl_xor_sync(0xffffffffu, l0, 1);
        l0 += __shfl_xor_sync(0xffffffffu, l0, 2);
        l1 += __shfl_xor_sync(0xffffffffu, l1, 1);
        l1 += __shfl_xor_sync(0xffffffffu, l1, 2);

        const int pb = (b * SPL + sp) * NP;
        #pragma unroll
        for (int j2 = 0; j2 < 4; j2++) {
            *(float2*)(g_acc + (pb + q0) * DI + 8 * j2 + 2 * t4) = make_float2(o[j2][0], o[j2][1]);
            *(float2*)(g_acc + (pb + q1) * DI + 8 * j2 + 2 * t4) = make_float2(o[j2][2], o[j2][3]);
        }
        if (t4 == 0) { g_lp[pb + q0] = l0; g_lp[pb + q1] = l1; }

        wi = nwi;
    }
}

// ---------------------------------------------------------------------------
// Stage 3: merge SPL partials + output projection + residual.
// ---------------------------------------------------------------------------
__global__ void __launch_bounds__(128) merge_kernel(
    const float* __restrict__ x,
    const float* __restrict__ w_w,
    float* __restrict__ out)
{
    __shared__ __align__(16) float ws[CH * DI];
    const int b = blockIdx.y, tid = threadIdx.x;
    const int n = blockIdx.x * 128 + tid;

    for (int i = tid; i < CH * DI; i += 128) ws[i] = w_w[i];
    __syncthreads();

    float l = 0.f;
    u64 y2[16];
    #pragma unroll
    for (int i = 0; i < 16; i++) y2[i] = 0ull;
    #pragma unroll 2
    for (int s = 0; s < SPL; s++) {
        l += g_lp[(b * SPL + s) * NP + n];
        const u64* ap = (const u64*)(g_acc + ((b * SPL + s) * NP + n) * DI);
        #pragma unroll
        for (int i2 = 0; i2 < 16; i2++) y2[i2] = f2add(y2[i2], ap[i2]);
    }
    const float inv = 1.f / l;
    u64 inv2; asm("mov.b64 %0,{%1,%1};" : "=l"(inv2) : "f"(inv));
    #pragma unroll
    for (int i2 = 0; i2 < 16; i2++) {
        u64 z = 0ull;
        y2[i2] = f2fma(y2[i2], inv2, z);
    }

    const float* xb = x + b * CH * NP + n;
    float* ob = out + b * CH * NP + n;
    #pragma unroll 2
    for (int c = 0; c < CH; c++) {
        const u64* w2 = (const u64*)(ws + c * DI);
        u64 o2 = 0ull;
        #pragma unroll
        for (int i2 = 0; i2 < 16; i2++) o2 = f2fma(w2[i2], y2[i2], o2);
        ob[c * NP] = xb[c * NP] + f2hadd(o2);
    }
}

// ---------------------------------------------------------------------------
extern "C" void kernel_launch(void* const* d_in, const int* in_sizes, int n_in,
                              void* d_out, int out_size)
{
    const float* x       = (const float*)d_in[0];
    const float* gw      = (const float*)d_in[1];
    const float* theta_w = (const float*)d_in[2];
    const float* phi_w   = (const float*)d_in[3];
    const float* w_w     = (const float*)d_in[4];
    float* out           = (float*)d_out;

    void* pm = nullptr; cudaGetSymbolAddress(&pm, g_phimax);
    cudaMemsetAsync(pm, 0, sizeof(unsigned) * BATCH);
    void* pc = nullptr; cudaGetSymbolAddress(&pc, g_ctr);
    cudaMemsetAsync(pc, 0, sizeof(unsigned));

    static int cfg = 0;
    if (!cfg) {
        cudaFuncSetAttribute(attn_kernel, cudaFuncAttributeMaxDynamicSharedMemorySize, ASMEM);
        cfg = 1;
    }

    dim3 gp(NP / PQ, 3, BATCH);
    proj_kernel<<<gp, 128>>>(x, theta_w, phi_w, gw);

    attn_kernel<<<296, 256, ASMEM>>>();

    dim3 gm(NP / 128, BATCH);
    merge_kernel<<<gm, 128>>>(x, w_w, out);
}